// round 13
// baseline (speedup 1.0000x reference)
#include <cuda_runtime.h>
#include <cuda_bf16.h>
#include <cstdint>

// ---------------------------------------------------------------------------
// Scratch (no allocs allowed).
// ---------------------------------------------------------------------------
__device__ unsigned short g_Ah[2 * 512 * 768];    // bf16 hi of [a;b], [z][m][k]
__device__ unsigned short g_Al[2 * 512 * 768];    // bf16 lo
__device__ unsigned short g_Wh[2 * 768 * 768];    // bf16 hi of W1, TRANSPOSED: [z][n][k]
__device__ unsigned short g_Wl[2 * 768 * 768];    // bf16 lo
__device__ float g_ab[2 * 512 * 768];             // [z][m][H] (z=0: ha+b1, z=1: hb)
__device__ float g_part[16 * 4 * 128 * 128 * 2];  // [hsplit][b][s][t][o]

// ---------------------------------------------------------------------------
// Warp-level bf16 MMA (base sm_80+ ISA; compiles under the harness's
// compute_103 target, unlike tcgen05 which needs the 'a' feature set).
// ---------------------------------------------------------------------------
__device__ __forceinline__ void mma16816(float* c, const uint32_t* a, const uint32_t* b) {
    asm volatile(
        "mma.sync.aligned.m16n8k16.row.col.f32.bf16.bf16.f32 "
        "{%0,%1,%2,%3}, {%4,%5,%6,%7}, {%8,%9}, {%0,%1,%2,%3};"
        : "+f"(c[0]), "+f"(c[1]), "+f"(c[2]), "+f"(c[3])
        : "r"(a[0]), "r"(a[1]), "r"(a[2]), "r"(a[3]), "r"(b[0]), "r"(b[1]));
}

// ---------------------------------------------------------------------------
// Fused conversion kernel (one launch):
//  blocks [0, 768):   [a;b] fp32 -> bf16 hi/lo, row-major [z][m][k]
//  blocks [768, 1920): W1 fp32 [1536][768] -> transposed bf16 hi/lo [z][n][k]
// ---------------------------------------------------------------------------
__global__ __launch_bounds__(256) void conv_kernel(const float* __restrict__ a,
                                                   const float* __restrict__ b,
                                                   const float* __restrict__ W1)
{
    const int tid = threadIdx.x;
    if (blockIdx.x < 768) {
        int i = blockIdx.x * 256 + tid;               // float4 index, < 196608
        const float* src = (i < 98304) ? (a + (size_t)i * 4) : (b + (size_t)(i - 98304) * 4);
        float4 v = *(const float4*)src;
        float x[4] = {v.x, v.y, v.z, v.w};
        ushort4 hv, lv;
        unsigned short* hp = &hv.x;
        unsigned short* lp = &lv.x;
        #pragma unroll
        for (int j = 0; j < 4; j++) {
            __nv_bfloat16 h = __float2bfloat16(x[j]);
            __nv_bfloat16 l = __float2bfloat16(x[j] - __bfloat162float(h));
            hp[j] = *(unsigned short*)&h;
            lp[j] = *(unsigned short*)&l;
        }
        *(ushort4*)(g_Ah + (size_t)i * 4) = hv;
        *(ushort4*)(g_Al + (size_t)i * 4) = lv;
    } else {
        __shared__ float tile[32][33];
        const int bxx = blockIdx.x - 768;             // 0..1151
        const int n0 = (bxx % 24) * 32;
        const int k0 = (bxx / 24) * 32;               // global k over 1536
        const int tx = tid & 31, ty = tid >> 5;       // (32, 8)
        #pragma unroll
        for (int i = 0; i < 4; i++)
            tile[ty + 8 * i][tx] = W1[(size_t)(k0 + ty + 8 * i) * 768 + n0 + tx];
        __syncthreads();
        const int z = (k0 >= 768) ? 1 : 0;
        const int kk = k0 - z * 768 + tx;             // k within z
        #pragma unroll
        for (int i = 0; i < 4; i++) {
            int n = n0 + ty + 8 * i;
            float x = tile[tx][ty + 8 * i];           // = W1[k0+tx][n]
            __nv_bfloat16 h = __float2bfloat16(x);
            __nv_bfloat16 l = __float2bfloat16(x - __bfloat162float(h));
            size_t o = (size_t)z * 768 * 768 + (size_t)n * 768 + kk;
            g_Wh[o] = *(unsigned short*)&h;
            g_Wl[o] = *(unsigned short*)&l;
        }
    }
}

// ---------------------------------------------------------------------------
// Tensor-core projection via mma.sync, pipelined:
//   g_ab[z][m][n] = sum_k A_z[m][k]*W1_z[k][n] (+b1 if z==0)
// bf16-split 3-term: Ah*Wh + Al*Wh + Ah*Wl.
// CTA: 64M x 32N, 128 threads = 4 warps (2x2), warp tile 32x16 (2x2 frags).
// K-chunks of 32 with REGISTER DOUBLE-BUFFER prefetch (LDG for chunk k+1
// issued before the MMAs of chunk k -> global latency hidden).
// Grid (8, 24, 2) = 384 CTAs (~2.6/SM, ~15KB smem -> several co-resident).
// ---------------------------------------------------------------------------
__global__ __launch_bounds__(128) void mma_proj_kernel(const float* __restrict__ b1)
{
    __shared__ __align__(16) unsigned short AsH[64][40];
    __shared__ __align__(16) unsigned short AsL[64][40];
    __shared__ __align__(16) unsigned short WsH[32][40];
    __shared__ __align__(16) unsigned short WsL[32][40];

    const int tid = threadIdx.x;
    const int wid = tid >> 5;
    const int lid = tid & 31;
    const int g = lid >> 2;              // fragment row group 0..7
    const int t = lid & 3;               // thread-in-group 0..3
    const int m0 = blockIdx.x * 64;
    const int n0 = blockIdx.y * 32;
    const int z  = blockIdx.z;
    const int wm = (wid & 1) * 32;
    const int wn = (wid >> 1) * 16;

    const unsigned short* __restrict__ Ah = g_Ah + (size_t)z * 512 * 768;
    const unsigned short* __restrict__ Al = g_Al + (size_t)z * 512 * 768;
    const unsigned short* __restrict__ Wh = g_Wh + (size_t)z * 768 * 768;
    const unsigned short* __restrict__ Wl = g_Wl + (size_t)z * 768 * 768;

    float acc[2][2][4];
    #pragma unroll
    for (int mf = 0; mf < 2; mf++)
        #pragma unroll
        for (int nf = 0; nf < 2; nf++)
            #pragma unroll
            for (int q = 0; q < 4; q++) acc[mf][nf][q] = 0.f;

    // Load mapping: 128 threads cover A (64 rows x 32 k, 2 uint4/thread per
    // hi/lo) and W (32 rows x 32 k, 1 uint4/thread per hi/lo).
    const int ar = tid >> 2;             // 0..31
    const int akq = (tid & 3) * 8;       // 0,8,16,24

    uint4 pAh[2], pAl[2], pWh, pWl;
    {
        const size_t ga0 = (size_t)(m0 + ar) * 768 + akq;
        const size_t ga1 = (size_t)(m0 + 32 + ar) * 768 + akq;
        const size_t gw  = (size_t)(n0 + ar) * 768 + akq;
        pAh[0] = *(const uint4*)(Ah + ga0); pAh[1] = *(const uint4*)(Ah + ga1);
        pAl[0] = *(const uint4*)(Al + ga0); pAl[1] = *(const uint4*)(Al + ga1);
        pWh = *(const uint4*)(Wh + gw);     pWl = *(const uint4*)(Wl + gw);
    }

    #pragma unroll 1
    for (int kb = 0; kb < 768; kb += 32) {
        __syncthreads();
        *(uint4*)&AsH[ar][akq]      = pAh[0];
        *(uint4*)&AsH[ar + 32][akq] = pAh[1];
        *(uint4*)&AsL[ar][akq]      = pAl[0];
        *(uint4*)&AsL[ar + 32][akq] = pAl[1];
        *(uint4*)&WsH[ar][akq]      = pWh;
        *(uint4*)&WsL[ar][akq]      = pWl;
        __syncthreads();

        if (kb + 32 < 768) {
            const size_t ga0 = (size_t)(m0 + ar) * 768 + kb + 32 + akq;
            const size_t ga1 = (size_t)(m0 + 32 + ar) * 768 + kb + 32 + akq;
            const size_t gw  = (size_t)(n0 + ar) * 768 + kb + 32 + akq;
            pAh[0] = *(const uint4*)(Ah + ga0); pAh[1] = *(const uint4*)(Ah + ga1);
            pAl[0] = *(const uint4*)(Al + ga0); pAl[1] = *(const uint4*)(Al + ga1);
            pWh = *(const uint4*)(Wh + gw);     pWl = *(const uint4*)(Wl + gw);
        }

        #pragma unroll
        for (int ks = 0; ks < 2; ks++) {
            const int k0 = ks * 16 + t * 2;
            uint32_t ah[2][4], al[2][4], bh[2][2], bl[2][2];
            #pragma unroll
            for (int mf = 0; mf < 2; mf++) {
                int mb = wm + mf * 16 + g;
                ah[mf][0] = *(const uint32_t*)&AsH[mb][k0];
                ah[mf][1] = *(const uint32_t*)&AsH[mb + 8][k0];
                ah[mf][2] = *(const uint32_t*)&AsH[mb][k0 + 8];
                ah[mf][3] = *(const uint32_t*)&AsH[mb + 8][k0 + 8];
                al[mf][0] = *(const uint32_t*)&AsL[mb][k0];
                al[mf][1] = *(const uint32_t*)&AsL[mb + 8][k0];
                al[mf][2] = *(const uint32_t*)&AsL[mb][k0 + 8];
                al[mf][3] = *(const uint32_t*)&AsL[mb + 8][k0 + 8];
            }
            #pragma unroll
            for (int nf = 0; nf < 2; nf++) {
                int nb = wn + nf * 8 + g;
                bh[nf][0] = *(const uint32_t*)&WsH[nb][k0];
                bh[nf][1] = *(const uint32_t*)&WsH[nb][k0 + 8];
                bl[nf][0] = *(const uint32_t*)&WsL[nb][k0];
                bl[nf][1] = *(const uint32_t*)&WsL[nb][k0 + 8];
            }
            #pragma unroll
            for (int mf = 0; mf < 2; mf++)
                #pragma unroll
                for (int nf = 0; nf < 2; nf++) {
                    mma16816(acc[mf][nf], ah[mf], bh[nf]);
                    mma16816(acc[mf][nf], al[mf], bh[nf]);
                    mma16816(acc[mf][nf], ah[mf], bl[nf]);
                }
        }
    }

    // Epilogue: d0/d1 = row g cols 2t,2t+1; d2/d3 = row g+8.
    float* C = g_ab + (size_t)z * 512 * 768;
    #pragma unroll
    for (int mf = 0; mf < 2; mf++) {
        int mr = m0 + wm + mf * 16 + g;
        #pragma unroll
        for (int nf = 0; nf < 2; nf++) {
            int n = n0 + wn + nf * 8 + t * 2;
            float2 add = make_float2(0.f, 0.f);
            if (z == 0) add = *(const float2*)(b1 + n);
            *(float2*)(C + (size_t)mr * 768 + n) =
                make_float2(acc[mf][nf][0] + add.x, acc[mf][nf][1] + add.y);
            *(float2*)(C + (size_t)(mr + 8) * 768 + n) =
                make_float2(acc[mf][nf][2] + add.x, acc[mf][nf][3] + add.y);
        }
    }
}

// ---------------------------------------------------------------------------
// Pairwise epilogue: part[hz][b][s][t][o] = sum_{h in chunk} relu(ha[s][h]+hb[t][h]) * W2[h][o]
// 32(s) x 64(t) tile, 256 threads, per-thread 2x4 pairs, H split 16 ways
// (chunk=48, single smem load + single sync). Grid (8, 4, 16) = 512 blocks.
// ---------------------------------------------------------------------------
__global__ __launch_bounds__(256) void pair_kernel(const float* __restrict__ W2)
{
    const int bx = blockIdx.x;           // 4 s-tiles x 2 t-tiles
    const int bb = blockIdx.y;           // batch
    const int bz = blockIdx.z;           // h split
    const int s0 = (bx & 3) * 32;
    const int t0 = (bx >> 2) * 64;
    const int h0 = bz * 48;

    const float* __restrict__ ha = g_ab + (bb * 128 + s0) * 768 + h0;
    const float* __restrict__ hb = g_ab + 512 * 768 + (bb * 128 + t0) * 768 + h0;

    __shared__ float  sha[48][36];       // [k][s], rows 144B (16B-aligned)
    __shared__ float  shb[48][68];       // [k][t], rows 272B (16B-aligned)
    __shared__ float2 sw2[48];

    const int tid = threadIdx.x;
    const int tx = tid & 15;             // 16 t-groups of 4
    const int ty = tid >> 4;             // 16 s-groups of 2

    float acc[2][4][2];
    #pragma unroll
    for (int i = 0; i < 2; i++)
        #pragma unroll
        for (int j = 0; j < 4; j++) { acc[i][j][0] = 0.f; acc[i][j][1] = 0.f; }

    // Fill smem: sha 32x48 (384 float4), shb 64x48 (768 float4), w 48.
    for (int f = tid; f < 384; f += 256) {
        int si = f / 12, kq = (f % 12) * 4;
        float4 v = *(const float4*)(ha + (size_t)si * 768 + kq);
        sha[kq + 0][si] = v.x; sha[kq + 1][si] = v.y;
        sha[kq + 2][si] = v.z; sha[kq + 3][si] = v.w;
    }
    #pragma unroll
    for (int q = 0; q < 3; q++) {
        int f = tid + q * 256;
        int si = f / 12, kq = (f % 12) * 4;
        float4 w = *(const float4*)(hb + (size_t)si * 768 + kq);
        shb[kq + 0][si] = w.x; shb[kq + 1][si] = w.y;
        shb[kq + 2][si] = w.z; shb[kq + 3][si] = w.w;
    }
    if (tid < 48) sw2[tid] = *(const float2*)(W2 + (h0 + tid) * 2);
    __syncthreads();

    #pragma unroll 4
    for (int k = 0; k < 48; k++) {
        float a0 = sha[k][ty * 2];
        float a1 = sha[k][ty * 2 + 1];
        float4 bv = *(const float4*)&shb[k][tx * 4];
        float2 w  = sw2[k];
        float aa[2] = {a0, a1};
        float bb4[4] = {bv.x, bv.y, bv.z, bv.w};
        #pragma unroll
        for (int i = 0; i < 2; i++)
            #pragma unroll
            for (int j = 0; j < 4; j++) {
                float x = aa[i] + bb4[j];
                float v = fmaxf(x, 0.0f);
                acc[i][j][0] += v * w.x;
                acc[i][j][1] += v * w.y;
            }
    }

    float* P = g_part + (size_t)(bz * 4 + bb) * (128 * 128 * 2);
    #pragma unroll
    for (int i = 0; i < 2; i++)
        #pragma unroll
        for (int j = 0; j < 4; j++) {
            int s = s0 + ty * 2 + i;
            int t = t0 + tx * 4 + j;
            *(float2*)(P + ((size_t)s * 128 + t) * 2) = make_float2(acc[i][j][0], acc[i][j][1]);
        }
}

// ---------------------------------------------------------------------------
// Reduce the 16 h-split partials + output bias. float4 per thread (2 pairs).
// ---------------------------------------------------------------------------
__global__ __launch_bounds__(128) void reduce_kernel(const float* __restrict__ b2,
                                                     float* __restrict__ out)
{
    int idx = blockIdx.x * 128 + threadIdx.x;   // 0..32767, 2 pairs each
    float2 bb = *(const float2*)b2;
    float4 acc = make_float4(bb.x, bb.y, bb.x, bb.y);
    #pragma unroll
    for (int zz = 0; zz < 16; zz++) {
        float4 p = *(const float4*)(g_part + (size_t)zz * (4 * 128 * 128 * 2) + (size_t)idx * 4);
        acc.x += p.x; acc.y += p.y; acc.z += p.z; acc.w += p.w;
    }
    *(float4*)(out + (size_t)idx * 4) = acc;
}

extern "C" void kernel_launch(void* const* d_in, const int* in_sizes, int n_in,
                              void* d_out, int out_size)
{
    const float* a  = (const float*)d_in[0];
    const float* b  = (const float*)d_in[1];
    const float* W1 = (const float*)d_in[2];
    const float* b1 = (const float*)d_in[3];
    const float* W2 = (const float*)d_in[4];
    const float* b2 = (const float*)d_in[5];
    float* out = (float*)d_out;

    conv_kernel<<<1920, 256>>>(a, b, W1);
    mma_proj_kernel<<<dim3(8, 24, 2), 128>>>(b1);
    pair_kernel<<<dim3(8, 4, 16), 256>>>(W2);
    reduce_kernel<<<256, 128>>>(b2, out);
}

// round 14
// speedup vs baseline: 1.6892x; 1.6892x over previous
#include <cuda_runtime.h>
#include <cuda_bf16.h>
#include <cstdint>

// ---------------------------------------------------------------------------
// Scratch (no allocs allowed).
// ---------------------------------------------------------------------------
__device__ unsigned short g_Ah[2 * 512 * 768];   // bf16 hi of [a;b], [z][m][k]
__device__ unsigned short g_Al[2 * 512 * 768];   // bf16 lo
__device__ unsigned short g_Wh[2 * 768 * 768];   // bf16 hi of W1, TRANSPOSED: [z][n][k]
__device__ unsigned short g_Wl[2 * 768 * 768];   // bf16 lo
__device__ float g_ab[2 * 512 * 768];            // [z][m][H] (z=0: ha+b1, z=1: hb)
__device__ float g_part[8 * 4 * 128 * 128 * 2];  // [hsplit][b][s][t][o]

// ---------------------------------------------------------------------------
// Warp-level bf16 MMA (base sm_80+ ISA; compiles under the harness's
// compute_103 target, unlike tcgen05 which needs the 'a' feature set).
// ---------------------------------------------------------------------------
__device__ __forceinline__ void mma16816(float* c, const uint32_t* a, const uint32_t* b) {
    asm volatile(
        "mma.sync.aligned.m16n8k16.row.col.f32.bf16.bf16.f32 "
        "{%0,%1,%2,%3}, {%4,%5,%6,%7}, {%8,%9}, {%0,%1,%2,%3};"
        : "+f"(c[0]), "+f"(c[1]), "+f"(c[2]), "+f"(c[3])
        : "r"(a[0]), "r"(a[1]), "r"(a[2]), "r"(a[3]), "r"(b[0]), "r"(b[1]));
}

// ---------------------------------------------------------------------------
// Fused conversion kernel (one launch):
//  blocks [0, 768):   [a;b] fp32 -> bf16 hi/lo, row-major [z][m][k]
//  blocks [768, 1920): W1 fp32 [1536][768] -> transposed bf16 hi/lo [z][n][k]
// ---------------------------------------------------------------------------
__global__ __launch_bounds__(256) void conv_kernel(const float* __restrict__ a,
                                                   const float* __restrict__ b,
                                                   const float* __restrict__ W1)
{
    const int tid = threadIdx.x;
    if (blockIdx.x < 768) {
        int i = blockIdx.x * 256 + tid;               // float4 index, < 196608
        const float* src = (i < 98304) ? (a + (size_t)i * 4) : (b + (size_t)(i - 98304) * 4);
        float4 v = *(const float4*)src;
        float x[4] = {v.x, v.y, v.z, v.w};
        ushort4 hv, lv;
        unsigned short* hp = &hv.x;
        unsigned short* lp = &lv.x;
        #pragma unroll
        for (int j = 0; j < 4; j++) {
            __nv_bfloat16 h = __float2bfloat16(x[j]);
            __nv_bfloat16 l = __float2bfloat16(x[j] - __bfloat162float(h));
            hp[j] = *(unsigned short*)&h;
            lp[j] = *(unsigned short*)&l;
        }
        *(ushort4*)(g_Ah + (size_t)i * 4) = hv;
        *(ushort4*)(g_Al + (size_t)i * 4) = lv;
    } else {
        __shared__ float tile[32][33];
        const int bxx = blockIdx.x - 768;             // 0..1151
        const int n0 = (bxx % 24) * 32;
        const int k0 = (bxx / 24) * 32;               // global k over 1536
        const int tx = tid & 31, ty = tid >> 5;       // (32, 8)
        #pragma unroll
        for (int i = 0; i < 4; i++)
            tile[ty + 8 * i][tx] = W1[(size_t)(k0 + ty + 8 * i) * 768 + n0 + tx];
        __syncthreads();
        const int z = (k0 >= 768) ? 1 : 0;
        const int kk = k0 - z * 768 + tx;             // k within z
        #pragma unroll
        for (int i = 0; i < 4; i++) {
            int n = n0 + ty + 8 * i;
            float x = tile[tx][ty + 8 * i];           // = W1[k0+tx][n]
            __nv_bfloat16 h = __float2bfloat16(x);
            __nv_bfloat16 l = __float2bfloat16(x - __bfloat162float(h));
            size_t o = (size_t)z * 768 * 768 + (size_t)n * 768 + kk;
            g_Wh[o] = *(unsigned short*)&h;
            g_Wl[o] = *(unsigned short*)&l;
        }
    }
}

// ---------------------------------------------------------------------------
// Tensor-core projection via mma.sync (R11 tiling + register prefetch):
//   g_ab[z][m][n] = sum_k A_z[m][k]*W1_z[k][n] (+b1 if z==0)
// bf16-split 3-term: Ah*Wh + Al*Wh + Ah*Wl (Al*Wl ~2^-16, dropped).
// CTA: 64M x 64N, 128 threads = 4 warps (2x2), warp tile 32x32 (2x4 frags).
// K-chunks of 32 with register double-buffer: LDG for chunk k+1 issued before
// the MMAs of chunk k (hides the ~600-cyc global latency that R11 exposed
// 24x per CTA).
// Grid (8, 12, 2) = 192 CTAs.
// ---------------------------------------------------------------------------
__global__ __launch_bounds__(128) void mma_proj_kernel(const float* __restrict__ b1)
{
    __shared__ __align__(16) unsigned short AsH[64][40];
    __shared__ __align__(16) unsigned short AsL[64][40];
    __shared__ __align__(16) unsigned short WsH[64][40];
    __shared__ __align__(16) unsigned short WsL[64][40];

    const int tid = threadIdx.x;
    const int wid = tid >> 5;
    const int lid = tid & 31;
    const int g = lid >> 2;              // fragment row group 0..7
    const int t = lid & 3;               // thread-in-group 0..3
    const int m0 = blockIdx.x * 64;
    const int n0 = blockIdx.y * 64;
    const int z  = blockIdx.z;
    const int wm = (wid & 1) * 32;
    const int wn = (wid >> 1) * 32;

    const unsigned short* __restrict__ Ah = g_Ah + (size_t)z * 512 * 768;
    const unsigned short* __restrict__ Al = g_Al + (size_t)z * 512 * 768;
    const unsigned short* __restrict__ Wh = g_Wh + (size_t)z * 768 * 768;
    const unsigned short* __restrict__ Wl = g_Wl + (size_t)z * 768 * 768;

    float acc[2][4][4];
    #pragma unroll
    for (int mf = 0; mf < 2; mf++)
        #pragma unroll
        for (int nf = 0; nf < 4; nf++)
            #pragma unroll
            for (int q = 0; q < 4; q++) acc[mf][nf][q] = 0.f;

    // Load mapping: 2 passes of 128 threads; row = v>>2 (0..63), kq = (v&3)*8.
    const int r0 = tid >> 2,        kq0 = (tid & 3) * 8;
    const int r1 = (tid + 128) >> 2, kq1 = kq0;        // second pass rows 32..63

    uint4 pAh[2], pAl[2], pWh[2], pWl[2];
    {
        const size_t ga0 = (size_t)(m0 + r0) * 768 + kq0;
        const size_t ga1 = (size_t)(m0 + r1) * 768 + kq1;
        const size_t gw0 = (size_t)(n0 + r0) * 768 + kq0;
        const size_t gw1 = (size_t)(n0 + r1) * 768 + kq1;
        pAh[0] = *(const uint4*)(Ah + ga0); pAh[1] = *(const uint4*)(Ah + ga1);
        pAl[0] = *(const uint4*)(Al + ga0); pAl[1] = *(const uint4*)(Al + ga1);
        pWh[0] = *(const uint4*)(Wh + gw0); pWh[1] = *(const uint4*)(Wh + gw1);
        pWl[0] = *(const uint4*)(Wl + gw0); pWl[1] = *(const uint4*)(Wl + gw1);
    }

    #pragma unroll 1
    for (int kb = 0; kb < 768; kb += 32) {
        __syncthreads();
        *(uint4*)&AsH[r0][kq0] = pAh[0];  *(uint4*)&AsH[r1][kq1] = pAh[1];
        *(uint4*)&AsL[r0][kq0] = pAl[0];  *(uint4*)&AsL[r1][kq1] = pAl[1];
        *(uint4*)&WsH[r0][kq0] = pWh[0];  *(uint4*)&WsH[r1][kq1] = pWh[1];
        *(uint4*)&WsL[r0][kq0] = pWl[0];  *(uint4*)&WsL[r1][kq1] = pWl[1];
        __syncthreads();

        if (kb + 32 < 768) {
            const size_t ga0 = (size_t)(m0 + r0) * 768 + kb + 32 + kq0;
            const size_t ga1 = (size_t)(m0 + r1) * 768 + kb + 32 + kq1;
            const size_t gw0 = (size_t)(n0 + r0) * 768 + kb + 32 + kq0;
            const size_t gw1 = (size_t)(n0 + r1) * 768 + kb + 32 + kq1;
            pAh[0] = *(const uint4*)(Ah + ga0); pAh[1] = *(const uint4*)(Ah + ga1);
            pAl[0] = *(const uint4*)(Al + ga0); pAl[1] = *(const uint4*)(Al + ga1);
            pWh[0] = *(const uint4*)(Wh + gw0); pWh[1] = *(const uint4*)(Wh + gw1);
            pWl[0] = *(const uint4*)(Wl + gw0); pWl[1] = *(const uint4*)(Wl + gw1);
        }

        #pragma unroll
        for (int ks = 0; ks < 2; ks++) {
            const int k0 = ks * 16 + t * 2;
            uint32_t ah[2][4], al[2][4], bh[4][2], bl[4][2];
            #pragma unroll
            for (int mf = 0; mf < 2; mf++) {
                int mb = wm + mf * 16 + g;
                ah[mf][0] = *(const uint32_t*)&AsH[mb][k0];
                ah[mf][1] = *(const uint32_t*)&AsH[mb + 8][k0];
                ah[mf][2] = *(const uint32_t*)&AsH[mb][k0 + 8];
                ah[mf][3] = *(const uint32_t*)&AsH[mb + 8][k0 + 8];
                al[mf][0] = *(const uint32_t*)&AsL[mb][k0];
                al[mf][1] = *(const uint32_t*)&AsL[mb + 8][k0];
                al[mf][2] = *(const uint32_t*)&AsL[mb][k0 + 8];
                al[mf][3] = *(const uint32_t*)&AsL[mb + 8][k0 + 8];
            }
            #pragma unroll
            for (int nf = 0; nf < 4; nf++) {
                int nb = wn + nf * 8 + g;
                bh[nf][0] = *(const uint32_t*)&WsH[nb][k0];
                bh[nf][1] = *(const uint32_t*)&WsH[nb][k0 + 8];
                bl[nf][0] = *(const uint32_t*)&WsL[nb][k0];
                bl[nf][1] = *(const uint32_t*)&WsL[nb][k0 + 8];
            }
            #pragma unroll
            for (int mf = 0; mf < 2; mf++)
                #pragma unroll
                for (int nf = 0; nf < 4; nf++) {
                    mma16816(acc[mf][nf], ah[mf], bh[nf]);
                    mma16816(acc[mf][nf], al[mf], bh[nf]);
                    mma16816(acc[mf][nf], ah[mf], bl[nf]);
                }
        }
    }

    // Epilogue: d0/d1 = row g cols 2t,2t+1; d2/d3 = row g+8.
    float* C = g_ab + (size_t)z * 512 * 768;
    #pragma unroll
    for (int mf = 0; mf < 2; mf++) {
        int mr = m0 + wm + mf * 16 + g;
        #pragma unroll
        for (int nf = 0; nf < 4; nf++) {
            int n = n0 + wn + nf * 8 + t * 2;
            float2 add = make_float2(0.f, 0.f);
            if (z == 0) add = *(const float2*)(b1 + n);
            *(float2*)(C + (size_t)mr * 768 + n) =
                make_float2(acc[mf][nf][0] + add.x, acc[mf][nf][1] + add.y);
            *(float2*)(C + (size_t)(mr + 8) * 768 + n) =
                make_float2(acc[mf][nf][2] + add.x, acc[mf][nf][3] + add.y);
        }
    }
}

// ---------------------------------------------------------------------------
// Pairwise epilogue: part[hz][b][s][t][o] = sum_{h in chunk} relu(ha[s][h]+hb[t][h]) * W2[h][o]
// 32(s) x 64(t) tile, 256 threads, per-thread 2x4 pairs, H split 8 ways
// (chunk=96, three 32-k phases). Grid (8, 4, 8) = 256 blocks (~1.7/SM; two
// ~13.5KB blocks co-reside per SM -> all SMs busy, vs 128 blocks in R11).
// ---------------------------------------------------------------------------
__global__ __launch_bounds__(256) void pair_kernel(const float* __restrict__ W2)
{
    const int bx = blockIdx.x;           // 4 s-tiles x 2 t-tiles
    const int bb = blockIdx.y;           // batch
    const int bz = blockIdx.z;           // h split
    const int s0 = (bx & 3) * 32;
    const int t0 = (bx >> 2) * 64;
    const int h0 = bz * 96;

    const float* __restrict__ ha = g_ab + (bb * 128 + s0) * 768 + h0;
    const float* __restrict__ hb = g_ab + 512 * 768 + (bb * 128 + t0) * 768 + h0;

    __shared__ float  sha[32][36];       // [k][s], rows 144B (16B-aligned)
    __shared__ float  shb[32][68];       // [k][t], rows 272B (16B-aligned)
    __shared__ float2 sw2[32];

    const int tid = threadIdx.x;
    const int tx = tid & 15;             // 16 t-groups of 4
    const int ty = tid >> 4;             // 16 s-groups of 2

    float acc[2][4][2];
    #pragma unroll
    for (int i = 0; i < 2; i++)
        #pragma unroll
        for (int j = 0; j < 4; j++) { acc[i][j][0] = 0.f; acc[i][j][1] = 0.f; }

    #pragma unroll 1
    for (int kb = 0; kb < 96; kb += 32) {
        __syncthreads();
        {   // sha: 32 s-rows x 32 k = 256 float4, one per thread
            int si = tid >> 3, kq = (tid & 7) * 4;
            float4 v = *(const float4*)(ha + (size_t)si * 768 + kb + kq);
            sha[kq + 0][si] = v.x; sha[kq + 1][si] = v.y;
            sha[kq + 2][si] = v.z; sha[kq + 3][si] = v.w;
        }
        #pragma unroll
        for (int i = 0; i < 2; i++) {    // shb: 64 t-rows x 32 k = 512 float4
            int f = tid + i * 256;
            int si = f >> 3, kq = (f & 7) * 4;
            float4 w = *(const float4*)(hb + (size_t)si * 768 + kb + kq);
            shb[kq + 0][si] = w.x; shb[kq + 1][si] = w.y;
            shb[kq + 2][si] = w.z; shb[kq + 3][si] = w.w;
        }
        if (tid < 32) sw2[tid] = *(const float2*)(W2 + (h0 + kb + tid) * 2);
        __syncthreads();

        #pragma unroll 4
        for (int k = 0; k < 32; k++) {
            float a0 = sha[k][ty * 2];
            float a1 = sha[k][ty * 2 + 1];
            float4 bv = *(const float4*)&shb[k][tx * 4];
            float2 w  = sw2[k];
            float aa[2] = {a0, a1};
            float bb4[4] = {bv.x, bv.y, bv.z, bv.w};
            #pragma unroll
            for (int i = 0; i < 2; i++)
                #pragma unroll
                for (int j = 0; j < 4; j++) {
                    float x = aa[i] + bb4[j];
                    float v = fmaxf(x, 0.0f);
                    acc[i][j][0] += v * w.x;
                    acc[i][j][1] += v * w.y;
                }
        }
    }

    float* P = g_part + (size_t)(bz * 4 + bb) * (128 * 128 * 2);
    #pragma unroll
    for (int i = 0; i < 2; i++)
        #pragma unroll
        for (int j = 0; j < 4; j++) {
            int s = s0 + ty * 2 + i;
            int t = t0 + tx * 4 + j;
            *(float2*)(P + ((size_t)s * 128 + t) * 2) = make_float2(acc[i][j][0], acc[i][j][1]);
        }
}

// ---------------------------------------------------------------------------
// Reduce the 8 h-split partials + output bias. float4 per thread (2 pairs).
// ---------------------------------------------------------------------------
__global__ __launch_bounds__(256) void reduce_kernel(const float* __restrict__ b2,
                                                     float* __restrict__ out)
{
    int idx = blockIdx.x * 256 + threadIdx.x;   // 0..32767, 2 pairs each
    float2 bb = *(const float2*)b2;
    float4 acc = make_float4(bb.x, bb.y, bb.x, bb.y);
    #pragma unroll
    for (int zz = 0; zz < 8; zz++) {
        float4 p = *(const float4*)(g_part + (size_t)zz * (4 * 128 * 128 * 2) + (size_t)idx * 4);
        acc.x += p.x; acc.y += p.y; acc.z += p.z; acc.w += p.w;
    }
    *(float4*)(out + (size_t)idx * 4) = acc;
}

extern "C" void kernel_launch(void* const* d_in, const int* in_sizes, int n_in,
                              void* d_out, int out_size)
{
    const float* a  = (const float*)d_in[0];
    const float* b  = (const float*)d_in[1];
    const float* W1 = (const float*)d_in[2];
    const float* b1 = (const float*)d_in[3];
    const float* W2 = (const float*)d_in[4];
    const float* b2 = (const float*)d_in[5];
    float* out = (float*)d_out;

    conv_kernel<<<1920, 256>>>(a, b, W1);
    mma_proj_kernel<<<dim3(8, 12, 2), 128>>>(b1);
    pair_kernel<<<dim3(8, 4, 8), 256>>>(W2);
    reduce_kernel<<<128, 256>>>(b2, out);
}